// round 14
// baseline (speedup 1.0000x reference)
#include <cuda_runtime.h>
#include <cstdint>
#include <cstring>

// Problem: N=32768 points, K=8192 centers, D=32. fp32 in, labels-as-fp32 out.
#define DIMS      32
#define KCENT     8192
#define TILE_N    256
#define NTILES    (KCENT / TILE_N)   // 32
#define THREADS   256                // 8 warps x 16 points
#define GRID      256                // 2 CTAs/SM
#define BPITCH    48                 // int8 row pitch in BOTH gmem and smem (conflict-free ldmatrix)
#define XPITCHW   36                 // x fp32 smem pitch words (144B)
#define QSX       22.5f
#define QSC2      22.5f
#define SCALEF    253.125f           // v_int = SCALEF*(c2 - 2 x.c)
#define MARGINI   600                // ~2.4 d2-units; quant err tail ~1.3
#define CAP       8192

// smem layout (bytes)
#define BUFSTRIDE  13312             // 256*48 qc tile (12288) + 1024 c2i
#define SM_X       39936             // 128*144 = 18432
#define SM_X2      58368             // 512
#define SM_BEST    58880             // 1024
#define SM_CNT     59904             // 16
#define SM_MBAR    59920             // 3 x 8
#define SM_LIST    59952             // 32768
#define SMEM_TOTAL 92720

__device__ __align__(16) uint8_t g_qc[(size_t)KCENT * BPITCH];  // int8(-22.5*c), 48B pitch (16B pad)
__device__ __align__(16) int   g_c2i[KCENT];                    // rni(SCALEF*||c||^2)
__device__ float g_c2f[KCENT];                                  // exact fp32 ||c||^2

__global__ void prep_centers(const float* __restrict__ c, int K) {
    int k = blockIdx.x * blockDim.x + threadIdx.x;
    if (k >= K) return;
    const float* row = c + (size_t)k * DIMS;
    float c2 = 0.0f;
    uint32_t w[8];
#pragma unroll
    for (int j = 0; j < 8; j++) {
        uint32_t pk = 0;
#pragma unroll
        for (int b = 0; b < 4; b++) {
            float v = row[4*j + b];
            c2 = fmaf(v, v, c2);
            int q = __float2int_rn(-QSC2 * v);
            q = max(-127, min(127, q));
            pk |= (uint32_t)(q & 0xFF) << (8 * b);
        }
        w[j] = pk;
    }
    uint4* dst = reinterpret_cast<uint4*>(g_qc + (size_t)k * BPITCH);
    dst[0] = make_uint4(w[0], w[1], w[2], w[3]);
    dst[1] = make_uint4(w[4], w[5], w[6], w[7]);
    dst[2] = make_uint4(0, 0, 0, 0);              // pad to 48B pitch
    g_c2i[k] = __float2int_rn(SCALEF * c2);
    g_c2f[k] = c2;
}

__device__ __forceinline__ uint32_t smem_u32(const void* p) {
    uint32_t a;
    asm("{ .reg .u64 t; cvta.to.shared.u64 t, %1; cvt.u32.u64 %0, t; }" : "=r"(a) : "l"(p));
    return a;
}
__device__ __forceinline__ void cp16(uint32_t dst, const void* src) {
    asm volatile("cp.async.cg.shared.global [%0], [%1], 16;" :: "r"(dst), "l"(src) : "memory");
}
__device__ __forceinline__ void mbar_init(uint32_t m, uint32_t cnt) {
    asm volatile("mbarrier.init.shared.b64 [%0], %1;" :: "r"(m), "r"(cnt) : "memory");
}
__device__ __forceinline__ void mbar_expect_tx(uint32_t m, uint32_t b) {
    asm volatile("mbarrier.arrive.expect_tx.shared.b64 _, [%0], %1;" :: "r"(m), "r"(b) : "memory");
}
__device__ __forceinline__ void mbar_wait(uint32_t m, uint32_t ph) {
    asm volatile(
        "{\n\t.reg .pred P1;\n\t"
        "W_%=:\n\t"
        "mbarrier.try_wait.parity.acquire.cta.shared::cta.b64 P1, [%0], %1, 0x989680;\n\t"
        "@P1 bra.uni D_%=;\n\t"
        "bra.uni W_%=;\n\t"
        "D_%=:\n\t}" :: "r"(m), "r"(ph) : "memory");
}
__device__ __forceinline__ void bulk_cp(uint32_t dst, const void* src, uint32_t bytes, uint32_t mbar) {
    asm volatile(
        "cp.async.bulk.shared::cta.global.mbarrier::complete_tx::bytes [%0], [%1], %2, [%3];"
        :: "r"(dst), "l"(src), "r"(bytes), "r"(mbar) : "memory");
}
#define MMAS8(d0,d1,d2,d3,a0,a1,a2,a3,b0,b1) \
    asm volatile("mma.sync.aligned.m16n8k32.row.col.s32.s8.s8.s32 " \
                 "{%0,%1,%2,%3}, {%4,%5,%6,%7}, {%8,%9}, {%0,%1,%2,%3};" \
                 : "+r"(d0), "+r"(d1), "+r"(d2), "+r"(d3) \
                 : "r"(a0), "r"(a1), "r"(a2), "r"(a3), "r"(b0), "r"(b1))

__device__ __forceinline__ uint32_t qpack4(const float* p) {
    uint32_t w = 0;
#pragma unroll
    for (int b = 0; b < 4; b++) {
        int q = __float2int_rn(QSX * p[b]);
        q = max(-127, min(127, q));
        w |= (uint32_t)(q & 0xFF) << (8 * b);
    }
    return w;
}

__device__ __forceinline__ void issue_tile(uint32_t sb, int t) {
    const uint32_t bufb = sb + (uint32_t)(t % 3) * BUFSTRIDE;
    const uint32_t mb = sb + SM_MBAR + (uint32_t)(t % 3) * 8;
    mbar_expect_tx(mb, TILE_N * BPITCH + TILE_N * 4);
    bulk_cp(bufb, g_qc + (size_t)t * (TILE_N * BPITCH), TILE_N * BPITCH, mb);   // pitched rows, linear copy
    bulk_cp(bufb + TILE_N * BPITCH,
            reinterpret_cast<const uint8_t*>(g_c2i) + (size_t)t * (TILE_N * 4),
            TILE_N * 4, mb);
}

__global__ __launch_bounds__(THREADS, 2)
void tc_label(float* __restrict__ out, const float* __restrict__ xg,
              const float* __restrict__ cg) {
    extern __shared__ uint8_t smem[];
    const uint32_t sb = smem_u32(smem);
    const int tid = threadIdx.x, lane = tid & 31, warp = tid >> 5;
    const int lm4 = lane & 3, r = lane >> 2;
    const int cta = blockIdx.x;

    float* sxf = reinterpret_cast<float*>(smem + SM_X);
    float* sx2 = reinterpret_cast<float*>(smem + SM_X2);
    unsigned long long* best = reinterpret_cast<unsigned long long*>(smem + SM_BEST);
    int* lcnt = reinterpret_cast<int*>(smem + SM_CNT);
    uint32_t* list = reinterpret_cast<uint32_t*>(smem + SM_LIST);

    if (tid < 128) best[tid] = 0xFFFFFFFFFFFFFFFFull;
    if (tid == 0) {
        *lcnt = 0;
        mbar_init(sb + SM_MBAR + 0, 1);
        mbar_init(sb + SM_MBAR + 8, 1);
        mbar_init(sb + SM_MBAR + 16, 1);
    }
    asm volatile("fence.proxy.async.shared::cta;" ::: "memory");
    __syncthreads();

    if (tid == 0) { issue_tile(sb, 0); issue_tile(sb, 1); }

    // x staging (one-time cp.async group)
    for (int i = tid; i < 128 * 8; i += THREADS) {
        int row = i >> 3, ch = i & 7;
        cp16(sb + SM_X + row * 144 + ch * 16,
             xg + (size_t)(cta * 128 + row) * DIMS + ch * 4);
    }
    asm volatile("cp.async.commit_group;" ::: "memory");
    asm volatile("cp.async.wait_group 0;" ::: "memory");
    __syncthreads();

    // A fragments + x2
    const int rowA = warp * 16 + r, rowB = rowA + 8;
    uint32_t A0, A1, A2, A3;
    {
        const float* x0 = sxf + rowA * XPITCHW;
        const float* x1 = sxf + rowB * XPITCHW;
        A0 = qpack4(x0 + 4 * lm4);
        A1 = qpack4(x1 + 4 * lm4);
        A2 = qpack4(x0 + 16 + 4 * lm4);
        A3 = qpack4(x1 + 16 + 4 * lm4);
    }
    if (tid < 128) {
        const float* xr = sxf + tid * XPITCHW;
        float s = 0.0f;
#pragma unroll
        for (int d = 0; d < DIMS; d++) s = fmaf(xr[d], xr[d], s);
        sx2[tid] = s;
    }
    __syncthreads();

    const uint32_t lmoff = (uint32_t)((lane & 7) + ((lane >> 4) << 3)) * BPITCH
                         + (uint32_t)(((lane >> 3) & 1) << 4);
    int thr0 = 0x7FFFFFFF, thr1 = 0x7FFFFFFF;

    // ---- prepass tile 0: warm thresholds (no pushes) ----
    mbar_wait(sb + SM_MBAR + 0, 0);
    {
        const int* c2s = reinterpret_cast<const int*>(smem + TILE_N * BPITCH);
#pragma unroll
        for (int pb = 0; pb < 16; pb++) {
            const uint32_t ba = sb + (uint32_t)pb * (16 * BPITCH) + lmoff;
            uint32_t b0, b1, b2, b3;
            asm volatile("ldmatrix.sync.aligned.m8n8.x4.shared.b16 {%0,%1,%2,%3}, [%4];"
                         : "=r"(b0), "=r"(b1), "=r"(b2), "=r"(b3) : "r"(ba));
            int2 ca = *reinterpret_cast<const int2*>(c2s + pb * 16 + 2 * lm4);
            int2 cb = *reinterpret_cast<const int2*>(c2s + pb * 16 + 8 + 2 * lm4);
            int u0 = ca.x, u1 = ca.y, u2 = ca.x, u3 = ca.y;
            int w0 = cb.x, w1 = cb.y, w2 = cb.x, w3 = cb.y;
            MMAS8(u0, u1, u2, u3, A0, A1, A2, A3, b0, b1);
            MMAS8(w0, w1, w2, w3, A0, A1, A2, A3, b2, b3);
            thr0 = min(thr0, min(min(u0, u1), min(w0, w1)) + MARGINI);
            thr1 = min(thr1, min(min(u2, u3), min(w2, w3)) + MARGINI);
        }
        thr0 = min(thr0, __shfl_xor_sync(~0u, thr0, 1));
        thr0 = min(thr0, __shfl_xor_sync(~0u, thr0, 2));
        thr1 = min(thr1, __shfl_xor_sync(~0u, thr1, 1));
        thr1 = min(thr1, __shfl_xor_sync(~0u, thr1, 2));
    }

    // ---- main loop ----
    for (int t = 0; t < NTILES; t++) {
        mbar_wait(sb + SM_MBAR + (uint32_t)(t % 3) * 8, (t / 3) & 1);
        __syncthreads();   // all warps done with tile t-1 -> slot (t+2)%3 free

        if (tid == 0 && t + 2 < NTILES) issue_tile(sb, t + 2);

        const uint32_t bufB = sb + (uint32_t)(t % 3) * BUFSTRIDE;
        const int* c2s = reinterpret_cast<const int*>(smem + (t % 3) * BUFSTRIDE + TILE_N * BPITCH);
        const int kb = t * TILE_N;

#pragma unroll
        for (int pb = 0; pb < 16; pb++) {
            const uint32_t ba = bufB + (uint32_t)pb * (16 * BPITCH) + lmoff;
            uint32_t b0, b1, b2, b3;
            asm volatile("ldmatrix.sync.aligned.m8n8.x4.shared.b16 {%0,%1,%2,%3}, [%4];"
                         : "=r"(b0), "=r"(b1), "=r"(b2), "=r"(b3) : "r"(ba));
            int2 ca = *reinterpret_cast<const int2*>(c2s + pb * 16 + 2 * lm4);
            int2 cb = *reinterpret_cast<const int2*>(c2s + pb * 16 + 8 + 2 * lm4);
            int u0 = ca.x, u1 = ca.y, u2 = ca.x, u3 = ca.y;
            int w0 = cb.x, w1 = cb.y, w2 = cb.x, w3 = cb.y;
            MMAS8(u0, u1, u2, u3, A0, A1, A2, A3, b0, b1);
            MMAS8(w0, w1, w2, w3, A0, A1, A2, A3, b2, b3);
            int bm0 = min(min(u0, u1), min(w0, w1));
            int bm1 = min(min(u2, u3), min(w2, w3));

            if (__any_sync(~0u, (bm0 < thr0) | (bm1 < thr1))) {
                const int k00 = kb + pb * 16 + 2 * lm4;
#define PUSH_IF(cond, rw, kk) \
                if (cond) { int pos = atomicAdd(lcnt, 1); \
                            if (pos < CAP) list[pos] = ((uint32_t)(rw) << 13) | (uint32_t)(kk); }
                PUSH_IF(u0 < thr0, rowA, k00)
                PUSH_IF(u1 < thr0, rowA, k00 + 1)
                PUSH_IF(w0 < thr0, rowA, k00 + 8)
                PUSH_IF(w1 < thr0, rowA, k00 + 9)
                PUSH_IF(u2 < thr1, rowB, k00)
                PUSH_IF(u3 < thr1, rowB, k00 + 1)
                PUSH_IF(w2 < thr1, rowB, k00 + 8)
                PUSH_IF(w3 < thr1, rowB, k00 + 9)
#undef PUSH_IF
            }
            thr0 = min(thr0, bm0 + MARGINI);
            thr1 = min(thr1, bm1 + MARGINI);
        }
        thr0 = min(thr0, __shfl_xor_sync(~0u, thr0, 1));
        thr0 = min(thr0, __shfl_xor_sync(~0u, thr0, 2));
        thr1 = min(thr1, __shfl_xor_sync(~0u, thr1, 1));
        thr1 = min(thr1, __shfl_xor_sync(~0u, thr1, 2));
    }

    // ---- cooperative exact refine ----
    __syncthreads();
    const int cnt = min(*lcnt, CAP);
    const int qid = lane >> 2, ql = lane & 3;
    for (int i0 = warp * 8; i0 < cnt; i0 += 64) {
        const int i = i0 + qid;
        const bool act = (i < cnt);
        const uint32_t e = act ? list[i] : 0u;
        const int row = e >> 13, k = e & 8191;
        const float4* cr = reinterpret_cast<const float4*>(cg + (size_t)k * DIMS);
        const float4* xr = reinterpret_cast<const float4*>(sxf + row * XPITCHW);
        float4 cca = cr[2*ql], ccb = cr[2*ql+1];
        float4 xa = xr[2*ql], xb = xr[2*ql+1];
        float p = cca.x * xa.x;
        p = fmaf(cca.y, xa.y, p); p = fmaf(cca.z, xa.z, p); p = fmaf(cca.w, xa.w, p);
        p = fmaf(ccb.x, xb.x, p); p = fmaf(ccb.y, xb.y, p);
        p = fmaf(ccb.z, xb.z, p); p = fmaf(ccb.w, xb.w, p);
        p += __shfl_xor_sync(~0u, p, 1);
        p += __shfl_xor_sync(~0u, p, 2);
        if (act && ql == 0) {
            float d2 = fmaf(-2.f, p, sx2[row]) + g_c2f[k];
            d2 = fmaxf(d2, 0.0f);
            unsigned long long key =
                ((unsigned long long)__float_as_uint(d2) << 32) | (unsigned)k;
            atomicMin(best + row, key);
        }
    }
    __syncthreads();
    if (tid < 128)
        out[cta * 128 + tid] = (float)(unsigned)(best[tid] & 8191ull);
}

extern "C" void kernel_launch(void* const* d_in, const int* in_sizes, int n_in,
                              void* d_out, int out_size) {
    const float* x; const float* c; int nx, nc;
    if (in_sizes[0] >= in_sizes[1]) { x = (const float*)d_in[0]; nx = in_sizes[0];
                                      c = (const float*)d_in[1]; nc = in_sizes[1]; }
    else                            { x = (const float*)d_in[1]; nx = in_sizes[1];
                                      c = (const float*)d_in[0]; nc = in_sizes[0]; }
    float* out = (float*)d_out;
    int K = nc / DIMS;

    prep_centers<<<(K + 127) / 128, 128>>>(c, K);

    cudaFuncSetAttribute(tc_label, cudaFuncAttributeMaxDynamicSharedMemorySize, SMEM_TOTAL);
    tc_label<<<GRID, THREADS, SMEM_TOTAL>>>(out, x, c);
}

// round 15
// speedup vs baseline: 1.0065x; 1.0065x over previous
#include <cuda_runtime.h>
#include <cstdint>
#include <cstring>

// Problem: N=32768 points, K=8192 centers, D=32. fp32 in, labels-as-fp32 out.
#define DIMS      32
#define KCENT     8192
#define TILE_N    256
#define NTILES    (KCENT / TILE_N)   // 32
#define THREADS   256                // 8 warps x 16 points
#define GRID      256                // 2 CTAs/SM
#define BPITCH    48                 // int8 row pitch gmem+smem (conflict-free ldmatrix)
#define XPITCHW   36                 // x fp32 smem pitch words (144B)
#define QSX       22.5f
#define QSC2      22.5f
#define SCALEF    253.125f           // v_int = SCALEF*(c2 - 2 x.c)
#define MARGINI   600                // ~2.4 d2-units; quant err tail ~1.3
#define CAP       12288              // larger: stale-threshold pushes are a superset

// smem layout (bytes)
#define BUFSTRIDE  13312             // 256*48 qc tile (12288) + 1024 c2i
#define SM_X       39936             // 128*144 = 18432
#define SM_X2      58368             // 512
#define SM_BEST    58880             // 1024
#define SM_CNT     59904             // 16
#define SM_MBAR    59920             // 3 x 8
#define SM_LIST    59952             // 12288*4 = 49152
#define SMEM_TOTAL 109104            // 2 CTAs/SM (218KB of 228KB)

__device__ __align__(16) uint8_t g_qc[(size_t)KCENT * BPITCH];  // int8(-22.5*c), 48B pitch
__device__ __align__(16) int   g_c2i[KCENT];                    // rni(SCALEF*||c||^2)
__device__ float g_c2f[KCENT];                                  // exact fp32 ||c||^2

__global__ void prep_centers(const float* __restrict__ c, int K) {
    int k = blockIdx.x * blockDim.x + threadIdx.x;
    if (k >= K) return;
    const float* row = c + (size_t)k * DIMS;
    float c2 = 0.0f;
    uint32_t w[8];
#pragma unroll
    for (int j = 0; j < 8; j++) {
        uint32_t pk = 0;
#pragma unroll
        for (int b = 0; b < 4; b++) {
            float v = row[4*j + b];
            c2 = fmaf(v, v, c2);
            int q = __float2int_rn(-QSC2 * v);
            q = max(-127, min(127, q));
            pk |= (uint32_t)(q & 0xFF) << (8 * b);
        }
        w[j] = pk;
    }
    uint4* dst = reinterpret_cast<uint4*>(g_qc + (size_t)k * BPITCH);
    dst[0] = make_uint4(w[0], w[1], w[2], w[3]);
    dst[1] = make_uint4(w[4], w[5], w[6], w[7]);
    dst[2] = make_uint4(0, 0, 0, 0);              // pad to 48B pitch
    g_c2i[k] = __float2int_rn(SCALEF * c2);
    g_c2f[k] = c2;
}

__device__ __forceinline__ uint32_t smem_u32(const void* p) {
    uint32_t a;
    asm("{ .reg .u64 t; cvta.to.shared.u64 t, %1; cvt.u32.u64 %0, t; }" : "=r"(a) : "l"(p));
    return a;
}
__device__ __forceinline__ void cp16(uint32_t dst, const void* src) {
    asm volatile("cp.async.cg.shared.global [%0], [%1], 16;" :: "r"(dst), "l"(src) : "memory");
}
__device__ __forceinline__ void mbar_init(uint32_t m, uint32_t cnt) {
    asm volatile("mbarrier.init.shared.b64 [%0], %1;" :: "r"(m), "r"(cnt) : "memory");
}
__device__ __forceinline__ void mbar_expect_tx(uint32_t m, uint32_t b) {
    asm volatile("mbarrier.arrive.expect_tx.shared.b64 _, [%0], %1;" :: "r"(m), "r"(b) : "memory");
}
__device__ __forceinline__ void mbar_wait(uint32_t m, uint32_t ph) {
    asm volatile(
        "{\n\t.reg .pred P1;\n\t"
        "W_%=:\n\t"
        "mbarrier.try_wait.parity.acquire.cta.shared::cta.b64 P1, [%0], %1, 0x989680;\n\t"
        "@P1 bra.uni D_%=;\n\t"
        "bra.uni W_%=;\n\t"
        "D_%=:\n\t}" :: "r"(m), "r"(ph) : "memory");
}
__device__ __forceinline__ void bulk_cp(uint32_t dst, const void* src, uint32_t bytes, uint32_t mbar) {
    asm volatile(
        "cp.async.bulk.shared::cta.global.mbarrier::complete_tx::bytes [%0], [%1], %2, [%3];"
        :: "r"(dst), "l"(src), "r"(bytes), "r"(mbar) : "memory");
}
#define MMAS8(d0,d1,d2,d3,a0,a1,a2,a3,b0,b1) \
    asm volatile("mma.sync.aligned.m16n8k32.row.col.s32.s8.s8.s32 " \
                 "{%0,%1,%2,%3}, {%4,%5,%6,%7}, {%8,%9}, {%0,%1,%2,%3};" \
                 : "+r"(d0), "+r"(d1), "+r"(d2), "+r"(d3) \
                 : "r"(a0), "r"(a1), "r"(a2), "r"(a3), "r"(b0), "r"(b1))
#define LDSMX4(b0,b1,b2,b3,addr) \
    asm volatile("ldmatrix.sync.aligned.m8n8.x4.shared.b16 {%0,%1,%2,%3}, [%4];" \
                 : "=r"(b0), "=r"(b1), "=r"(b2), "=r"(b3) : "r"(addr))

__device__ __forceinline__ uint32_t qpack4(const float* p) {
    uint32_t w = 0;
#pragma unroll
    for (int b = 0; b < 4; b++) {
        int q = __float2int_rn(QSX * p[b]);
        q = max(-127, min(127, q));
        w |= (uint32_t)(q & 0xFF) << (8 * b);
    }
    return w;
}

__device__ __forceinline__ void issue_tile(uint32_t sb, int t) {
    const uint32_t bufb = sb + (uint32_t)(t % 3) * BUFSTRIDE;
    const uint32_t mb = sb + SM_MBAR + (uint32_t)(t % 3) * 8;
    mbar_expect_tx(mb, TILE_N * BPITCH + TILE_N * 4);
    bulk_cp(bufb, g_qc + (size_t)t * (TILE_N * BPITCH), TILE_N * BPITCH, mb);
    bulk_cp(bufb + TILE_N * BPITCH,
            reinterpret_cast<const uint8_t*>(g_c2i) + (size_t)t * (TILE_N * 4),
            TILE_N * 4, mb);
}

__global__ __launch_bounds__(THREADS, 2)
void tc_label(float* __restrict__ out, const float* __restrict__ xg,
              const float* __restrict__ cg) {
    extern __shared__ uint8_t smem[];
    const uint32_t sb = smem_u32(smem);
    const int tid = threadIdx.x, lane = tid & 31, warp = tid >> 5;
    const int lm4 = lane & 3, r = lane >> 2;
    const int cta = blockIdx.x;

    float* sxf = reinterpret_cast<float*>(smem + SM_X);
    float* sx2 = reinterpret_cast<float*>(smem + SM_X2);
    unsigned long long* best = reinterpret_cast<unsigned long long*>(smem + SM_BEST);
    int* lcnt = reinterpret_cast<int*>(smem + SM_CNT);
    uint32_t* list = reinterpret_cast<uint32_t*>(smem + SM_LIST);

    if (tid < 128) best[tid] = 0xFFFFFFFFFFFFFFFFull;
    if (tid == 0) {
        *lcnt = 0;
        mbar_init(sb + SM_MBAR + 0, 1);
        mbar_init(sb + SM_MBAR + 8, 1);
        mbar_init(sb + SM_MBAR + 16, 1);
    }
    asm volatile("fence.proxy.async.shared::cta;" ::: "memory");
    __syncthreads();

    if (tid == 0) { issue_tile(sb, 0); issue_tile(sb, 1); }

    // x staging (one-time cp.async group)
    for (int i = tid; i < 128 * 8; i += THREADS) {
        int row = i >> 3, ch = i & 7;
        cp16(sb + SM_X + row * 144 + ch * 16,
             xg + (size_t)(cta * 128 + row) * DIMS + ch * 4);
    }
    asm volatile("cp.async.commit_group;" ::: "memory");
    asm volatile("cp.async.wait_group 0;" ::: "memory");
    __syncthreads();

    // A fragments + x2
    const int rowA = warp * 16 + r, rowB = rowA + 8;
    uint32_t A0, A1, A2, A3;
    {
        const float* x0 = sxf + rowA * XPITCHW;
        const float* x1 = sxf + rowB * XPITCHW;
        A0 = qpack4(x0 + 4 * lm4);
        A1 = qpack4(x1 + 4 * lm4);
        A2 = qpack4(x0 + 16 + 4 * lm4);
        A3 = qpack4(x1 + 16 + 4 * lm4);
    }
    if (tid < 128) {
        const float* xr = sxf + tid * XPITCHW;
        float s = 0.0f;
#pragma unroll
        for (int d = 0; d < DIMS; d++) s = fmaf(xr[d], xr[d], s);
        sx2[tid] = s;
    }
    __syncthreads();

    const uint32_t lmoff = (uint32_t)((lane & 7) + ((lane >> 4) << 3)) * BPITCH
                         + (uint32_t)(((lane >> 3) & 1) << 4);
    int thr0 = 0x7FFFFFFF, thr1 = 0x7FFFFFFF;

    // ---- prepass tile 0: warm thresholds (pure min, no pushes) ----
    mbar_wait(sb + SM_MBAR + 0, 0);
    {
        const int* c2s = reinterpret_cast<const int*>(smem + TILE_N * BPITCH);
        int tm0 = 0x7FFFFFFF, tm1 = 0x7FFFFFFF;
#pragma unroll
        for (int pb = 0; pb < 16; pb++) {
            const uint32_t ba = sb + (uint32_t)pb * (16 * BPITCH) + lmoff;
            uint32_t b0, b1, b2, b3;
            LDSMX4(b0, b1, b2, b3, ba);
            int2 ca = *reinterpret_cast<const int2*>(c2s + pb * 16 + 2 * lm4);
            int2 cb = *reinterpret_cast<const int2*>(c2s + pb * 16 + 8 + 2 * lm4);
            int u0 = ca.x, u1 = ca.y, u2 = ca.x, u3 = ca.y;
            int w0 = cb.x, w1 = cb.y, w2 = cb.x, w3 = cb.y;
            MMAS8(u0, u1, u2, u3, A0, A1, A2, A3, b0, b1);
            MMAS8(w0, w1, w2, w3, A0, A1, A2, A3, b2, b3);
            tm0 = min(tm0, min(min(u0, u1), min(w0, w1)));
            tm1 = min(tm1, min(min(u2, u3), min(w2, w3)));
        }
        thr0 = tm0 + MARGINI;
        thr1 = tm1 + MARGINI;
        thr0 = min(thr0, __shfl_xor_sync(~0u, thr0, 1));
        thr0 = min(thr0, __shfl_xor_sync(~0u, thr0, 2));
        thr1 = min(thr1, __shfl_xor_sync(~0u, thr1, 1));
        thr1 = min(thr1, __shfl_xor_sync(~0u, thr1, 2));
    }

    // ---- main loop ----
    for (int t = 0; t < NTILES; t++) {
        mbar_wait(sb + SM_MBAR + (uint32_t)(t % 3) * 8, (t / 3) & 1);
        __syncthreads();   // all warps done with tile t-1 -> slot (t+2)%3 free

        if (tid == 0 && t + 2 < NTILES) issue_tile(sb, t + 2);

        const uint32_t bufB = sb + (uint32_t)(t % 3) * BUFSTRIDE;
        const int* c2s = reinterpret_cast<const int*>(smem + (t % 3) * BUFSTRIDE + TILE_N * BPITCH);
        const int kb = t * TILE_N;

        // ---- phase 1: pure screen (branchless; fully pipelineable) ----
        int bm0a[16], bm1a[16];
#pragma unroll
        for (int pb = 0; pb < 16; pb++) {
            const uint32_t ba = bufB + (uint32_t)pb * (16 * BPITCH) + lmoff;
            uint32_t b0, b1, b2, b3;
            LDSMX4(b0, b1, b2, b3, ba);
            int2 ca = *reinterpret_cast<const int2*>(c2s + pb * 16 + 2 * lm4);
            int2 cb = *reinterpret_cast<const int2*>(c2s + pb * 16 + 8 + 2 * lm4);
            int u0 = ca.x, u1 = ca.y, u2 = ca.x, u3 = ca.y;
            int w0 = cb.x, w1 = cb.y, w2 = cb.x, w3 = cb.y;
            MMAS8(u0, u1, u2, u3, A0, A1, A2, A3, b0, b1);
            MMAS8(w0, w1, w2, w3, A0, A1, A2, A3, b2, b3);
            bm0a[pb] = min(min(u0, u1), min(w0, w1));
            bm1a[pb] = min(min(u2, u3), min(w2, w3));
        }

        // ---- phase 2: deferred trigger scan (tile-start thresholds = conservative) ----
        const int thr0s = thr0, thr1s = thr1;
        uint32_t trig = 0;
        int tm0 = 0x7FFFFFFF, tm1 = 0x7FFFFFFF;
#pragma unroll
        for (int pb = 0; pb < 16; pb++) {
            tm0 = min(tm0, bm0a[pb]);
            tm1 = min(tm1, bm1a[pb]);
            trig |= (uint32_t)((bm0a[pb] < thr0s) | (bm1a[pb] < thr1s)) << pb;
        }

        if (__any_sync(~0u, trig != 0)) {
#pragma unroll 1
            for (int pb = 0; pb < 16; pb++) {
                if (!__any_sync(~0u, (trig >> pb) & 1)) continue;
                // recompute this block and push
                const uint32_t ba = bufB + (uint32_t)pb * (16 * BPITCH) + lmoff;
                uint32_t b0, b1, b2, b3;
                LDSMX4(b0, b1, b2, b3, ba);
                int2 ca = *reinterpret_cast<const int2*>(c2s + pb * 16 + 2 * lm4);
                int2 cb = *reinterpret_cast<const int2*>(c2s + pb * 16 + 8 + 2 * lm4);
                int u0 = ca.x, u1 = ca.y, u2 = ca.x, u3 = ca.y;
                int w0 = cb.x, w1 = cb.y, w2 = cb.x, w3 = cb.y;
                MMAS8(u0, u1, u2, u3, A0, A1, A2, A3, b0, b1);
                MMAS8(w0, w1, w2, w3, A0, A1, A2, A3, b2, b3);
                const int k00 = kb + pb * 16 + 2 * lm4;
#define PUSH_IF(cond, rw, kk) \
                if (cond) { int pos = atomicAdd(lcnt, 1); \
                            if (pos < CAP) list[pos] = ((uint32_t)(rw) << 13) | (uint32_t)(kk); }
                PUSH_IF(u0 < thr0s, rowA, k00)
                PUSH_IF(u1 < thr0s, rowA, k00 + 1)
                PUSH_IF(w0 < thr0s, rowA, k00 + 8)
                PUSH_IF(w1 < thr0s, rowA, k00 + 9)
                PUSH_IF(u2 < thr1s, rowB, k00)
                PUSH_IF(u3 < thr1s, rowB, k00 + 1)
                PUSH_IF(w2 < thr1s, rowB, k00 + 8)
                PUSH_IF(w3 < thr1s, rowB, k00 + 9)
#undef PUSH_IF
            }
        }

        // tighten thresholds once per tile + quad exchange
        thr0 = min(thr0, tm0 + MARGINI);
        thr1 = min(thr1, tm1 + MARGINI);
        thr0 = min(thr0, __shfl_xor_sync(~0u, thr0, 1));
        thr0 = min(thr0, __shfl_xor_sync(~0u, thr0, 2));
        thr1 = min(thr1, __shfl_xor_sync(~0u, thr1, 1));
        thr1 = min(thr1, __shfl_xor_sync(~0u, thr1, 2));
    }

    // ---- cooperative exact refine ----
    __syncthreads();
    const int cnt = min(*lcnt, CAP);
    const int qid = lane >> 2, ql = lane & 3;
    for (int i0 = warp * 8; i0 < cnt; i0 += 64) {
        const int i = i0 + qid;
        const bool act = (i < cnt);
        const uint32_t e = act ? list[i] : 0u;
        const int row = e >> 13, k = e & 8191;
        const float4* cr = reinterpret_cast<const float4*>(cg + (size_t)k * DIMS);
        const float4* xr = reinterpret_cast<const float4*>(sxf + row * XPITCHW);
        float4 cca = cr[2*ql], ccb = cr[2*ql+1];
        float4 xa = xr[2*ql], xb = xr[2*ql+1];
        float p = cca.x * xa.x;
        p = fmaf(cca.y, xa.y, p); p = fmaf(cca.z, xa.z, p); p = fmaf(cca.w, xa.w, p);
        p = fmaf(ccb.x, xb.x, p); p = fmaf(ccb.y, xb.y, p);
        p = fmaf(ccb.z, xb.z, p); p = fmaf(ccb.w, xb.w, p);
        p += __shfl_xor_sync(~0u, p, 1);
        p += __shfl_xor_sync(~0u, p, 2);
        if (act && ql == 0) {
            float d2 = fmaf(-2.f, p, sx2[row]) + g_c2f[k];
            d2 = fmaxf(d2, 0.0f);
            unsigned long long key =
                ((unsigned long long)__float_as_uint(d2) << 32) | (unsigned)k;
            atomicMin(best + row, key);
        }
    }
    __syncthreads();
    if (tid < 128)
        out[cta * 128 + tid] = (float)(unsigned)(best[tid] & 8191ull);
}

extern "C" void kernel_launch(void* const* d_in, const int* in_sizes, int n_in,
                              void* d_out, int out_size) {
    const float* x; const float* c; int nx, nc;
    if (in_sizes[0] >= in_sizes[1]) { x = (const float*)d_in[0]; nx = in_sizes[0];
                                      c = (const float*)d_in[1]; nc = in_sizes[1]; }
    else                            { x = (const float*)d_in[1]; nx = in_sizes[1];
                                      c = (const float*)d_in[0]; nc = in_sizes[0]; }
    float* out = (float*)d_out;
    int K = nc / DIMS;

    prep_centers<<<(K + 127) / 128, 128>>>(c, K);

    cudaFuncSetAttribute(tc_label, cudaFuncAttributeMaxDynamicSharedMemorySize, SMEM_TOTAL);
    tc_label<<<GRID, THREADS, SMEM_TOTAL>>>(out, x, c);
}

// round 16
// speedup vs baseline: 1.0940x; 1.0869x over previous
#include <cuda_runtime.h>
#include <cstdint>
#include <cstring>

// Problem: N=32768 points, K=8192 centers, D=32. fp32 in, labels-as-fp32 out.
#define DIMS      32
#define KCENT     8192
#define TILE_N    128
#define NTILES    (KCENT / TILE_N)   // 64
#define THREADS   256                // 8 warps x 16 points
#define GRID      256                // 2 CTAs/SM
#define BPITCH    48                 // int8 row pitch (conflict-free ldmatrix)
#define XPITCHW   36                 // x fp32 smem pitch words (144B)
#define QSX       22.5f
#define QSC2      22.5f
#define SCALEF    253.125f           // v_int = SCALEF*(c2 - 2 x.c)
#define MARGINI   600                // ~2.4 d2-units; quant err tail ~1.3
#define CAP       8192

// smem layout (bytes) — R12 layout + sample tile appended
#define BUFSTRIDE  6656              // 128*48 qc tile + 512 c2i
#define SM_X       19968             // 128*144 = 18432
#define SM_X2      38400             // 512
#define SM_BEST    38912             // 1024
#define SM_CNT     39936             // 16
#define SM_LIST    39952             // 8192*4 = 32768
#define SM_SAMP    72720             // 128*48 + 512 = 6656
#define SMEM_TOTAL 79376             // 2 CTAs/SM

__device__ __align__(16) uint8_t g_qc[(size_t)KCENT * 32];   // int8(-22.5*c), packed 32B
__device__ __align__(16) int   g_c2i[KCENT];                 // rni(SCALEF*||c||^2)
__device__ float g_c2f[KCENT];                               // exact fp32 ||c||^2
__device__ __align__(16) uint8_t g_samp[6656];               // 128 strided centers: qc(48B pitch)+c2i

__global__ void prep_centers(const float* __restrict__ c, int K) {
    int k = blockIdx.x * blockDim.x + threadIdx.x;
    if (k >= K) return;
    const float* row = c + (size_t)k * DIMS;
    float c2 = 0.0f;
    uint32_t w[8];
#pragma unroll
    for (int j = 0; j < 8; j++) {
        uint32_t pk = 0;
#pragma unroll
        for (int b = 0; b < 4; b++) {
            float v = row[4*j + b];
            c2 = fmaf(v, v, c2);
            int q = __float2int_rn(-QSC2 * v);
            q = max(-127, min(127, q));
            pk |= (uint32_t)(q & 0xFF) << (8 * b);
        }
        w[j] = pk;
    }
    uint4* dst = reinterpret_cast<uint4*>(g_qc + (size_t)k * 32);
    dst[0] = make_uint4(w[0], w[1], w[2], w[3]);
    dst[1] = make_uint4(w[4], w[5], w[6], w[7]);
    int c2q = __float2int_rn(SCALEF * c2);
    g_c2i[k] = c2q;
    g_c2f[k] = c2;
    if ((k & 63) == 0) {             // strided global sample, 48B pitch
        int j = k >> 6;              // 0..127
        uint4* sdst = reinterpret_cast<uint4*>(g_samp + (size_t)j * BPITCH);
        sdst[0] = make_uint4(w[0], w[1], w[2], w[3]);
        sdst[1] = make_uint4(w[4], w[5], w[6], w[7]);
        sdst[2] = make_uint4(0, 0, 0, 0);
        reinterpret_cast<int*>(g_samp + 6144)[j] = c2q;
    }
}

__device__ __forceinline__ uint32_t smem_u32(const void* p) {
    uint32_t a;
    asm("{ .reg .u64 t; cvta.to.shared.u64 t, %1; cvt.u32.u64 %0, t; }" : "=r"(a) : "l"(p));
    return a;
}
__device__ __forceinline__ void cp16(uint32_t dst, const void* src) {
    asm volatile("cp.async.cg.shared.global [%0], [%1], 16;" :: "r"(dst), "l"(src) : "memory");
}
#define MMAS8(d0,d1,d2,d3,a0,a1,a2,a3,b0,b1) \
    asm volatile("mma.sync.aligned.m16n8k32.row.col.s32.s8.s8.s32 " \
                 "{%0,%1,%2,%3}, {%4,%5,%6,%7}, {%8,%9}, {%0,%1,%2,%3};" \
                 : "+r"(d0), "+r"(d1), "+r"(d2), "+r"(d3) \
                 : "r"(a0), "r"(a1), "r"(a2), "r"(a3), "r"(b0), "r"(b1))
#define LDSMX4(b0,b1,b2,b3,addr) \
    asm volatile("ldmatrix.sync.aligned.m8n8.x4.shared.b16 {%0,%1,%2,%3}, [%4];" \
                 : "=r"(b0), "=r"(b1), "=r"(b2), "=r"(b3) : "r"(addr))

__device__ __forceinline__ uint32_t qpack4(const float* p) {
    uint32_t w = 0;
#pragma unroll
    for (int b = 0; b < 4; b++) {
        int q = __float2int_rn(QSX * p[b]);
        q = max(-127, min(127, q));
        w |= (uint32_t)(q & 0xFF) << (8 * b);
    }
    return w;
}

__global__ __launch_bounds__(THREADS, 2)
void tc_label(float* __restrict__ out, const float* __restrict__ xg,
              const float* __restrict__ cg) {
    extern __shared__ uint8_t smem[];
    const uint32_t sb = smem_u32(smem);
    const int tid = threadIdx.x, lane = tid & 31, warp = tid >> 5;
    const int lm4 = lane & 3, r = lane >> 2;
    const int cta = blockIdx.x;

    float* sxf = reinterpret_cast<float*>(smem + SM_X);
    float* sx2 = reinterpret_cast<float*>(smem + SM_X2);
    unsigned long long* best = reinterpret_cast<unsigned long long*>(smem + SM_BEST);
    int* lcnt = reinterpret_cast<int*>(smem + SM_CNT);
    uint32_t* list = reinterpret_cast<uint32_t*>(smem + SM_LIST);

    if (tid < 128) best[tid] = 0xFFFFFFFFFFFFFFFFull;
    if (tid == 0) *lcnt = 0;

    // group 1: x staging + sample tile
    for (int i = tid; i < 128 * 8 + 416; i += THREADS) {
        if (i < 128 * 8) {
            int row = i >> 3, ch = i & 7;
            cp16(sb + SM_X + row * 144 + ch * 16,
                 xg + (size_t)(cta * 128 + row) * DIMS + ch * 4);
        } else {
            int j = i - 128 * 8;      // 0..415 -> 416 x 16B = 6656 B linear
            cp16(sb + SM_SAMP + j * 16, g_samp + j * 16);
        }
    }
    asm volatile("cp.async.commit_group;" ::: "memory");

    // B-tile loader: qc (512 chunks of 16B over 48B-pitch smem) + c2i (32)
    auto issue = [&](int t) {
        const uint32_t bufb = sb + (uint32_t)(t % 3) * BUFSTRIDE;
        for (int i = tid; i < 288; i += THREADS) {
            if (i < 256) {
                int row = i >> 1, ch = i & 1;
                cp16(bufb + row * BPITCH + ch * 16, g_qc + (size_t)t * 4096 + i * 16);
            } else {
                int j = i - 256;
                cp16(bufb + 6144 + j * 16,
                     reinterpret_cast<const uint8_t*>(g_c2i) + t * 512 + j * 16);
            }
        }
        asm volatile("cp.async.commit_group;" ::: "memory");
    };
    issue(0);
    issue(1);

    asm volatile("cp.async.wait_group 2;" ::: "memory");   // x + sample done
    __syncthreads();

    // A fragments + x2
    const int rowA = warp * 16 + r, rowB = rowA + 8;
    uint32_t A0, A1, A2, A3;
    {
        const float* x0 = sxf + rowA * XPITCHW;
        const float* x1 = sxf + rowB * XPITCHW;
        A0 = qpack4(x0 + 4 * lm4);
        A1 = qpack4(x1 + 4 * lm4);
        A2 = qpack4(x0 + 16 + 4 * lm4);
        A3 = qpack4(x1 + 16 + 4 * lm4);
    }
    if (tid < 128) {
        const float* xr = sxf + tid * XPITCHW;
        float s = 0.0f;
#pragma unroll
        for (int d = 0; d < DIMS; d++) s = fmaf(xr[d], xr[d], s);
        sx2[tid] = s;
    }
    __syncthreads();

    const uint32_t lmoff = (uint32_t)((lane & 7) + ((lane >> 4) << 3)) * BPITCH
                         + (uint32_t)(((lane >> 3) & 1) << 4);

    // ---- GLOBAL-SAMPLE prepass: seed thresholds near the true min ----
    int thr0, thr1;
    {
        const int* c2s = reinterpret_cast<const int*>(smem + SM_SAMP + 6144);
        int tm0 = 0x7FFFFFFF, tm1 = 0x7FFFFFFF;
#pragma unroll
        for (int pb = 0; pb < 8; pb++) {
            const uint32_t ba = sb + SM_SAMP + (uint32_t)pb * (16 * BPITCH) + lmoff;
            uint32_t b0, b1, b2, b3;
            LDSMX4(b0, b1, b2, b3, ba);
            int2 ca = *reinterpret_cast<const int2*>(c2s + pb * 16 + 2 * lm4);
            int2 cb = *reinterpret_cast<const int2*>(c2s + pb * 16 + 8 + 2 * lm4);
            int u0 = ca.x, u1 = ca.y, u2 = ca.x, u3 = ca.y;
            int w0 = cb.x, w1 = cb.y, w2 = cb.x, w3 = cb.y;
            MMAS8(u0, u1, u2, u3, A0, A1, A2, A3, b0, b1);
            MMAS8(w0, w1, w2, w3, A0, A1, A2, A3, b2, b3);
            tm0 = min(tm0, min(min(u0, u1), min(w0, w1)));
            tm1 = min(tm1, min(min(u2, u3), min(w2, w3)));
        }
        thr0 = tm0 + MARGINI;
        thr1 = tm1 + MARGINI;
        thr0 = min(thr0, __shfl_xor_sync(~0u, thr0, 1));
        thr0 = min(thr0, __shfl_xor_sync(~0u, thr0, 2));
        thr1 = min(thr1, __shfl_xor_sync(~0u, thr1, 1));
        thr1 = min(thr1, __shfl_xor_sync(~0u, thr1, 2));
    }

    // ---- main loop (R12 structure) ----
    for (int t = 0; t < NTILES; t++) {
        if (t < NTILES - 1) asm volatile("cp.async.wait_group 1;" ::: "memory");
        else                asm volatile("cp.async.wait_group 0;" ::: "memory");
        __syncthreads();

        const uint32_t bufB = sb + (uint32_t)(t % 3) * BUFSTRIDE;
        const int* c2s = reinterpret_cast<const int*>(smem + (t % 3) * BUFSTRIDE + 6144);
        const int kb = t * TILE_N;

#pragma unroll
        for (int pb = 0; pb < 8; pb++) {
            const uint32_t ba = bufB + (uint32_t)pb * (16 * BPITCH) + lmoff;
            uint32_t b0, b1, b2, b3;
            LDSMX4(b0, b1, b2, b3, ba);
            int2 ca = *reinterpret_cast<const int2*>(c2s + pb * 16 + 2 * lm4);
            int2 cb = *reinterpret_cast<const int2*>(c2s + pb * 16 + 8 + 2 * lm4);
            int u0 = ca.x, u1 = ca.y, u2 = ca.x, u3 = ca.y;
            int w0 = cb.x, w1 = cb.y, w2 = cb.x, w3 = cb.y;
            MMAS8(u0, u1, u2, u3, A0, A1, A2, A3, b0, b1);
            MMAS8(w0, w1, w2, w3, A0, A1, A2, A3, b2, b3);
            int bm0 = min(min(u0, u1), min(w0, w1));
            int bm1 = min(min(u2, u3), min(w2, w3));

            if (__any_sync(~0u, (bm0 < thr0) | (bm1 < thr1))) {
                const int k00 = kb + pb * 16 + 2 * lm4;
#define PUSH_IF(cond, rw, kk) \
                if (cond) { int pos = atomicAdd(lcnt, 1); \
                            if (pos < CAP) list[pos] = ((uint32_t)(rw) << 13) | (uint32_t)(kk); }
                PUSH_IF(u0 < thr0, rowA, k00)
                PUSH_IF(u1 < thr0, rowA, k00 + 1)
                PUSH_IF(w0 < thr0, rowA, k00 + 8)
                PUSH_IF(w1 < thr0, rowA, k00 + 9)
                PUSH_IF(u2 < thr1, rowB, k00)
                PUSH_IF(u3 < thr1, rowB, k00 + 1)
                PUSH_IF(w2 < thr1, rowB, k00 + 8)
                PUSH_IF(w3 < thr1, rowB, k00 + 9)
#undef PUSH_IF
            }
            thr0 = min(thr0, bm0 + MARGINI);
            thr1 = min(thr1, bm1 + MARGINI);
        }
        thr0 = min(thr0, __shfl_xor_sync(~0u, thr0, 1));
        thr0 = min(thr0, __shfl_xor_sync(~0u, thr0, 2));
        thr1 = min(thr1, __shfl_xor_sync(~0u, thr1, 1));
        thr1 = min(thr1, __shfl_xor_sync(~0u, thr1, 2));

        if (t + 2 < NTILES) issue(t + 2);
    }

    // ---- cooperative exact refine (one candidate per quad, fp32) ----
    __syncthreads();
    const int cnt = min(*lcnt, CAP);
    const int qid = lane >> 2, ql = lane & 3;
    for (int i0 = warp * 8; i0 < cnt; i0 += 64) {
        const int i = i0 + qid;
        const bool act = (i < cnt);
        const uint32_t e = act ? list[i] : 0u;
        const int row = e >> 13, k = e & 8191;
        const float4* cr = reinterpret_cast<const float4*>(cg + (size_t)k * DIMS);
        const float4* xr = reinterpret_cast<const float4*>(sxf + row * XPITCHW);
        float4 cca = cr[2*ql], ccb = cr[2*ql+1];
        float4 xa = xr[2*ql], xb = xr[2*ql+1];
        float p = cca.x * xa.x;
        p = fmaf(cca.y, xa.y, p); p = fmaf(cca.z, xa.z, p); p = fmaf(cca.w, xa.w, p);
        p = fmaf(ccb.x, xb.x, p); p = fmaf(ccb.y, xb.y, p);
        p = fmaf(ccb.z, xb.z, p); p = fmaf(ccb.w, xb.w, p);
        p += __shfl_xor_sync(~0u, p, 1);
        p += __shfl_xor_sync(~0u, p, 2);
        if (act && ql == 0) {
            float d2 = fmaf(-2.f, p, sx2[row]) + g_c2f[k];
            d2 = fmaxf(d2, 0.0f);
            unsigned long long key =
                ((unsigned long long)__float_as_uint(d2) << 32) | (unsigned)k;
            atomicMin(best + row, key);
        }
    }
    __syncthreads();
    if (tid < 128)
        out[cta * 128 + tid] = (float)(unsigned)(best[tid] & 8191ull);
}

extern "C" void kernel_launch(void* const* d_in, const int* in_sizes, int n_in,
                              void* d_out, int out_size) {
    const float* x; const float* c; int nx, nc;
    if (in_sizes[0] >= in_sizes[1]) { x = (const float*)d_in[0]; nx = in_sizes[0];
                                      c = (const float*)d_in[1]; nc = in_sizes[1]; }
    else                            { x = (const float*)d_in[1]; nx = in_sizes[1];
                                      c = (const float*)d_in[0]; nc = in_sizes[0]; }
    float* out = (float*)d_out;
    int K = nc / DIMS;

    prep_centers<<<(K + 127) / 128, 128>>>(c, K);

    cudaFuncSetAttribute(tc_label, cudaFuncAttributeMaxDynamicSharedMemorySize, SMEM_TOTAL);
    tc_label<<<GRID, THREADS, SMEM_TOTAL>>>(out, x, c);
}